// round 4
// baseline (speedup 1.0000x reference)
#include <cuda_runtime.h>
#include <cstdint>

#define HDIM 512
#define TILE 32
#define NT   512
#define KC   32
#define CP   516    // Ws row stride (floats), padded
#define HP   516    // h row stride (floats), padded

__device__ float g_sf[2][4][HDIM];

__device__ __forceinline__ void fma2(unsigned long long &d, unsigned long long a, unsigned long long b){
    asm("fma.rn.f32x2 %0, %1, %2, %0;" : "+l"(d) : "l"(a), "l"(b));
}
__device__ __forceinline__ unsigned long long dup2(float v){
    unsigned long long r; asm("mov.b64 %0, {%1,%1};" : "=l"(r) : "f"(v)); return r;
}
__device__ __forceinline__ float2 unpk(unsigned long long v){
    float2 f; asm("mov.b64 {%0,%1}, %2;" : "=f"(f.x), "=f"(f.y) : "l"(v)); return f;
}

// sf[f][b][:] = tanh(code[b] @ cond_w^T + cond_b)
__global__ void sf_kernel(const float* __restrict__ code,
                          const float* __restrict__ cw1, const float* __restrict__ cb1,
                          const float* __restrict__ cw2, const float* __restrict__ cb2){
    int b = blockIdx.x, f = blockIdx.y, t = threadIdx.x;
    const float* cw = f ? cw2 : cw1;
    const float* cb = f ? cb2 : cb1;
    const float4* c4 = reinterpret_cast<const float4*>(code + b*HDIM);
    const float4* w4 = reinterpret_cast<const float4*>(cw + t*HDIM);
    float s = 0.f;
    #pragma unroll 4
    for (int i = 0; i < HDIM/4; i++){
        float4 a = c4[i], w = w4[i];
        s = fmaf(a.x, w.x, fmaf(a.y, w.y, fmaf(a.z, w.z, fmaf(a.w, w.w, s))));
    }
    g_sf[f][b][t] = tanhf(s + cb[t]);
}

// One residual GEMM stage: h = relu(h @ W^T + bias) + h   (h: TILE x HDIM in smem)
__device__ __forceinline__ void gemm_res(
    float* __restrict__ h, float* __restrict__ Ws,
    const float* __restrict__ W, const float* __restrict__ bias_s,
    int tid, int r0, int c0)
{
    unsigned long long acc[4][4];
    #pragma unroll
    for (int i = 0; i < 4; ++i)
        #pragma unroll
        for (int j = 0; j < 4; ++j) acc[i][j] = 0ull;

    const int sk = tid & 31;        // k within chunk (coalesced LDG lane)
    const int scq = tid >> 5;       // col-quad group 0..15

    for (int k0 = 0; k0 < HDIM; k0 += KC){
        __syncthreads();            // Ws free, h (for first chunk: stage outputs) visible
        // ---- stage W chunk into smem k-major: Ws[k][c]
        #pragma unroll
        for (int p = 0; p < 8; ++p){
            int c4 = (p*16 + scq)*4;
            float4 w;
            w.x = W[(c4+0)*HDIM + k0 + sk];
            w.y = W[(c4+1)*HDIM + k0 + sk];
            w.z = W[(c4+2)*HDIM + k0 + sk];
            w.w = W[(c4+3)*HDIM + k0 + sk];
            *reinterpret_cast<float4*>(&Ws[sk*CP + c4]) = w;
        }
        __syncthreads();
        // ---- compute chunk
        #pragma unroll 2
        for (int kk = 0; kk < KC; kk += 4){
            float4 hv[4];
            #pragma unroll
            for (int i = 0; i < 4; ++i)
                hv[i] = *reinterpret_cast<const float4*>(&h[(r0 + 4*i)*HP + k0 + kk]);
            #pragma unroll
            for (int t2 = 0; t2 < 4; ++t2){
                ulonglong2 bA = *reinterpret_cast<const ulonglong2*>(&Ws[(kk+t2)*CP + c0]);
                ulonglong2 bB = *reinterpret_cast<const ulonglong2*>(&Ws[(kk+t2)*CP + c0 + 4]);
                #pragma unroll
                for (int i = 0; i < 4; ++i){
                    float hs = (t2==0) ? hv[i].x : (t2==1) ? hv[i].y : (t2==2) ? hv[i].z : hv[i].w;
                    unsigned long long ad = dup2(hs);
                    fma2(acc[i][0], ad, bA.x);
                    fma2(acc[i][1], ad, bA.y);
                    fma2(acc[i][2], ad, bB.x);
                    fma2(acc[i][3], ad, bB.y);
                }
            }
        }
    }

    // ---- epilogue: relu + bias + residual  (acc[i][j] = cols c0+2j, c0+2j+1)
    float nv[4][8];
    #pragma unroll
    for (int i = 0; i < 4; ++i){
        int r = r0 + 4*i;
        #pragma unroll
        for (int j = 0; j < 4; ++j){
            float2 s = unpk(acc[i][j]);
            int ce = c0 + 2*j;
            nv[i][2*j]   = fmaxf(s.x + bias_s[ce],   0.f) + h[r*HP + ce];
            nv[i][2*j+1] = fmaxf(s.y + bias_s[ce+1], 0.f) + h[r*HP + ce + 1];
        }
    }
    __syncthreads();   // all threads done reading old h
    #pragma unroll
    for (int i = 0; i < 4; ++i){
        int r = r0 + 4*i;
        *reinterpret_cast<float4*>(&h[r*HP + c0])     = make_float4(nv[i][0], nv[i][1], nv[i][2], nv[i][3]);
        *reinterpret_cast<float4*>(&h[r*HP + c0 + 4]) = make_float4(nv[i][4], nv[i][5], nv[i][6], nv[i][7]);
    }
    // NOTE: caller must sync before next read of h (gemm's chunk-sync or explicit)
}

__global__ __launch_bounds__(NT, 1)
void deform_kernel(const float* __restrict__ x_in, float* __restrict__ x_out,
    const float* __restrict__ W1a, const float* __restrict__ b1a,
    const float* __restrict__ W2a, const float* __restrict__ b2a,
    const float* __restrict__ W3a, const float* __restrict__ b3a,
    const float* __restrict__ W4a, const float* __restrict__ b4a,
    const float* __restrict__ W1b, const float* __restrict__ b1b,
    const float* __restrict__ W2b, const float* __restrict__ b2b,
    const float* __restrict__ W3b, const float* __restrict__ b3b,
    const float* __restrict__ W4b, const float* __restrict__ b4b)
{
    extern __shared__ __align__(16) float smem[];
    float* h    = smem;                       // 32*516 = 16512 floats
    float* Ws   = smem + TILE*HP;             // 32*516 = 16512 floats
    float* sfs  = Ws + KC*CP;                 // 512
    float* b1s  = sfs + 512;
    float* b2s  = b1s + 512;
    float* b3s  = b2s + 512;
    float* w1xs = b3s + 512;
    float* w1ys = w1xs + 512;
    float* w1zs = w1ys + 512;
    float* w4s  = w1zs + 512;                 // 3*512

    __shared__ float p0[TILE][3], pe[TILE][3], ksum[TILE][3], kcur[TILE][3];

    const int tid = threadIdx.x;
    const int base = blockIdx.x * TILE;
    const int b = base >> 12;                 // 4096 rows per batch

    // thread's output tile: rows r0+{0,4,8,12}, cols c0..c0+7
    const int wr = (tid >> 5) & 1;
    const int wc = tid >> 6;
    const int rt = (tid >> 3) & 3;
    const int ct = tid & 7;
    const int r0 = wr*16 + rt;
    const int c0 = wc*64 + ct*8;

    if (tid < TILE*3){
        int r = tid/3, j = tid - r*3;
        float v = x_in[(base + r)*3 + j];
        p0[r][j] = v; pe[r][j] = v;
    }

    const float dt = 0.05f;   // TIME / N_STEPS

    for (int f = 0; f < 2; ++f){
        const float* W1 = f ? W1b : W1a;
        const float* B1 = f ? b1b : b1a;
        const float* W2 = f ? W2b : W2a;
        const float* B2 = f ? b2b : b2a;
        const float* W3 = f ? W3b : W3a;
        const float* B3 = f ? b3b : b3a;
        const float* W4 = f ? W4b : W4a;
        const float* B4 = f ? b4b : b4a;

        // per-f constant staging
        __syncthreads();
        {
            int c = tid;
            sfs[c]  = g_sf[f][b][c];
            b1s[c]  = B1[c]; b2s[c] = B2[c]; b3s[c] = B3[c];
            w1xs[c] = W1[c*3+0]; w1ys[c] = W1[c*3+1]; w1zs[c] = W1[c*3+2];
            w4s[c]        = W4[c];
            w4s[512 + c]  = W4[512 + c];
            w4s[1024 + c] = W4[1024 + c];
        }
        __syncthreads();

        for (int step = 0; step < 4; ++step){
            for (int s = 0; s < 4; ++s){
                // ---- stage 1: h = relu(pe @ W1^T + b1) * sf
                #pragma unroll
                for (int i = 0; i < 4; ++i){
                    int r = r0 + 4*i;
                    float px = pe[r][0], py = pe[r][1], pz = pe[r][2];
                    float vv[8];
                    #pragma unroll
                    for (int j = 0; j < 8; ++j){
                        int c = c0 + j;
                        float v = fmaf(px, w1xs[c], fmaf(py, w1ys[c], fmaf(pz, w1zs[c], b1s[c])));
                        vv[j] = fmaxf(v, 0.f) * sfs[c];
                    }
                    *reinterpret_cast<float4*>(&h[r*HP + c0])     = make_float4(vv[0],vv[1],vv[2],vv[3]);
                    *reinterpret_cast<float4*>(&h[r*HP + c0 + 4]) = make_float4(vv[4],vv[5],vv[6],vv[7]);
                }
                // (gemm's first chunk-sync orders these writes before reads)

                // ---- stages 2,3: residual GEMMs
                gemm_res(h, Ws, W2, b2s, tid, r0, c0);
                gemm_res(h, Ws, W3, b3s, tid, r0, c0);
                __syncthreads();   // h final before stage 4 reads

                // ---- stage 4: kcur = tanh(h @ W4^T + b4); warp w -> rows 2w, 2w+1
                {
                    const int w = tid >> 5, lane = tid & 31;
                    float a00=0.f,a01=0.f,a02=0.f,a10=0.f,a11=0.f,a12=0.f;
                    #pragma unroll 4
                    for (int ii = 0; ii < 16; ++ii){
                        int k = lane + ii*32;
                        float w0 = w4s[k], w1 = w4s[512+k], w2 = w4s[1024+k];
                        float h0 = h[(2*w)*HP + k];
                        float h1 = h[(2*w+1)*HP + k];
                        a00 = fmaf(h0, w0, a00); a01 = fmaf(h0, w1, a01); a02 = fmaf(h0, w2, a02);
                        a10 = fmaf(h1, w0, a10); a11 = fmaf(h1, w1, a11); a12 = fmaf(h1, w2, a12);
                    }
                    float av[6] = {a00, a01, a02, a10, a11, a12};
                    #pragma unroll
                    for (int j = 0; j < 6; ++j){
                        float v = av[j];
                        #pragma unroll
                        for (int off = 16; off > 0; off >>= 1)
                            v += __shfl_xor_sync(0xffffffffu, v, off);
                        if (lane == 0) kcur[2*w + (j/3)][j%3] = tanhf(v + B4[j%3]);
                    }
                }
                __syncthreads();

                // ---- RK4 state update
                if (tid < TILE*3){
                    int r = tid/3, j = tid - r*3;
                    float k = kcur[r][j];
                    if (s == 0){ ksum[r][j] = k;            pe[r][j] = fmaf(0.5f*dt, k, p0[r][j]); }
                    else if (s == 1){ ksum[r][j] += 2.f*k;  pe[r][j] = fmaf(0.5f*dt, k, p0[r][j]); }
                    else if (s == 2){ ksum[r][j] += 2.f*k;  pe[r][j] = fmaf(dt, k, p0[r][j]); }
                    else { float p = fmaf(dt/6.f, ksum[r][j] + k, p0[r][j]); p0[r][j] = p; pe[r][j] = p; }
                }
                __syncthreads();
            }
        }
    }

    if (tid < TILE*3){
        int r = tid/3, j = tid - r*3;
        x_out[(base + r)*3 + j] = p0[r][j];
    }
}

extern "C" void kernel_launch(void* const* d_in, const int* in_sizes, int n_in,
                              void* d_out, int out_size)
{
    const float* code   = (const float*)d_in[0];
    const float* x      = (const float*)d_in[1];
    const float* f1_l1w = (const float*)d_in[2];
    const float* f1_l1b = (const float*)d_in[3];
    const float* f1_l2w = (const float*)d_in[4];
    const float* f1_l2b = (const float*)d_in[5];
    const float* f1_l3w = (const float*)d_in[6];
    const float* f1_l3b = (const float*)d_in[7];
    const float* f1_l4w = (const float*)d_in[8];
    const float* f1_l4b = (const float*)d_in[9];
    const float* f1_cw  = (const float*)d_in[10];
    const float* f1_cb  = (const float*)d_in[11];
    const float* f2_l1w = (const float*)d_in[12];
    const float* f2_l1b = (const float*)d_in[13];
    const float* f2_l2w = (const float*)d_in[14];
    const float* f2_l2b = (const float*)d_in[15];
    const float* f2_l3w = (const float*)d_in[16];
    const float* f2_l3b = (const float*)d_in[17];
    const float* f2_l4w = (const float*)d_in[18];
    const float* f2_l4b = (const float*)d_in[19];
    const float* f2_cw  = (const float*)d_in[20];
    const float* f2_cb  = (const float*)d_in[21];
    float* out = (float*)d_out;

    const int smem_bytes = (TILE*HP + KC*CP + 7*512 + 3*512) * (int)sizeof(float);
    cudaFuncSetAttribute(deform_kernel, cudaFuncAttributeMaxDynamicSharedMemorySize, smem_bytes);

    sf_kernel<<<dim3(4, 2), HDIM>>>(code, f1_cw, f1_cb, f2_cw, f2_cb);

    const int n_blocks = (4 * 4096) / TILE;  // 512
    deform_kernel<<<n_blocks, NT, smem_bytes>>>(
        x, out,
        f1_l1w, f1_l1b, f1_l2w, f1_l2b, f1_l3w, f1_l3b, f1_l4w, f1_l4b,
        f2_l1w, f2_l1b, f2_l2w, f2_l2b, f2_l3w, f2_l3b, f2_l4w, f2_l4b);
}

// round 7
// speedup vs baseline: 5.0244x; 5.0244x over previous
#include <cuda_runtime.h>
#include <cstdint>

#define HDIM 512
#define ROWS 64          // rows per CTA
#define NT   512         // 16 warps
#define HP   516         // h row stride (floats), padded for conflict-free A-frag LDS
#define KCH  16          // K per chunk
#define NCH  32          // 512 / 16 chunks
#define WSW  (KCH*HDIM)  // words per W chunk buffer (8192 = 32KB)
#define CHBYTES (WSW*4)

__device__ float g_sf[2][4][HDIM];
// k-major, tf32-rounded, XOR-permuted W2/W3 for f1,f2: [mat][k*512 + (n ^ ((k&3)<<3))]
__device__ __align__(16) float g_wt[4][HDIM*HDIM];

// ---------------- helpers ----------------
__device__ __forceinline__ uint32_t smem_u32(const void* p){
    uint32_t a;
    asm("{ .reg .u64 t; cvta.to.shared.u64 t, %1; cvt.u32.u64 %0, t; }" : "=r"(a) : "l"(p));
    return a;
}
__device__ __forceinline__ float rna_tf32(float x){
    uint32_t u; asm("cvt.rna.tf32.f32 %0, %1;" : "=r"(u) : "f"(x));
    return __uint_as_float(u);
}
__device__ __forceinline__ void mbar_wait(uint32_t mbar, int parity){
    asm volatile(
        "{\n\t.reg .pred P;\n\t"
        "LAB%=:\n\t"
        "mbarrier.try_wait.parity.acquire.cta.shared::cta.b64 P, [%0], %1, 0x989680;\n\t"
        "@!P bra LAB%=;\n\t}"
        :: "r"(mbar), "r"(parity) : "memory");
}
#define MBAR_INIT(a, c)   asm volatile("mbarrier.init.shared.b64 [%0], %1;" :: "r"(a), "r"((uint32_t)(c)) : "memory")
#define MBAR_INVAL(a)     asm volatile("mbarrier.inval.shared.b64 [%0];" :: "r"(a) : "memory")
#define MBAR_EXPECT(a, b) asm volatile("mbarrier.arrive.expect_tx.shared.b64 _, [%0], %1;" :: "r"(a), "r"((uint32_t)(b)) : "memory")
#define BULK_G2S(dst, src, mbar) \
    asm volatile("cp.async.bulk.shared::cluster.global.mbarrier::complete_tx::bytes [%0], [%1], %2, [%3];" \
        :: "r"(dst), "l"(src), "r"((uint32_t)CHBYTES), "r"(mbar) : "memory")

__device__ __forceinline__ void mma_tf32(float& d0, float& d1, float& d2, float& d3,
                                         uint32_t a0, uint32_t a1, uint32_t a2, uint32_t a3,
                                         uint32_t b0, uint32_t b1){
    asm volatile("mma.sync.aligned.m16n8k8.row.col.f32.tf32.tf32.f32 "
        "{%0,%1,%2,%3}, {%4,%5,%6,%7}, {%8,%9}, {%0,%1,%2,%3};"
        : "+f"(d0), "+f"(d1), "+f"(d2), "+f"(d3)
        : "r"(a0), "r"(a1), "r"(a2), "r"(a3), "r"(b0), "r"(b1));
}

// ---------------- prep: transpose W2/W3 to k-major tf32 with XOR bank permute ----------------
__global__ void prep_kernel(const float* __restrict__ W2a, const float* __restrict__ W3a,
                            const float* __restrict__ W2b, const float* __restrict__ W3b){
    __shared__ float t[32][33];
    int mat = blockIdx.z;
    const float* W = mat==0 ? W2a : mat==1 ? W3a : mat==2 ? W2b : W3b;
    int n0 = blockIdx.x*32, k0 = blockIdx.y*32;
    int tx = threadIdx.x, ty = threadIdx.y;   // 32 x 8
    #pragma unroll
    for (int i = 0; i < 32; i += 8)
        t[ty+i][tx] = W[(n0+ty+i)*HDIM + k0 + tx];
    __syncthreads();
    #pragma unroll
    for (int i = 0; i < 32; i += 8){
        int k = k0 + ty + i;
        int n = n0 + tx;
        int np = n ^ ((k & 3) << 3);
        g_wt[mat][k*HDIM + np] = rna_tf32(t[tx][ty+i]);  // = W[n][k]
    }
}

// sf[f][b][:] = tanh(code[b] @ cond_w^T + cond_b)
__global__ void sf_kernel(const float* __restrict__ code,
                          const float* __restrict__ cw1, const float* __restrict__ cb1,
                          const float* __restrict__ cw2, const float* __restrict__ cb2){
    int b = blockIdx.x, f = blockIdx.y, t = threadIdx.x;
    const float* cw = f ? cw2 : cw1;
    const float* cb = f ? cb2 : cb1;
    const float4* c4 = reinterpret_cast<const float4*>(code + b*HDIM);
    const float4* w4 = reinterpret_cast<const float4*>(cw + t*HDIM);
    float s = 0.f;
    #pragma unroll 4
    for (int i = 0; i < HDIM/4; i++){
        float4 a = c4[i], w = w4[i];
        s = fmaf(a.x, w.x, fmaf(a.y, w.y, fmaf(a.z, w.z, fmaf(a.w, w.w, s))));
    }
    g_sf[f][b][t] = tanhf(s + cb[t]);
}

// one residual stage: h = relu(h @ W^T + bias) + h via tf32 mma.sync, bulk-async W stream
__device__ __forceinline__ void gemm_res(
    float* __restrict__ h, float* __restrict__ ws0, float* __restrict__ ws1,
    uint32_t ws0u, uint32_t ws1u,
    const float* __restrict__ Wt, const float* __restrict__ bias_s,
    uint32_t mbar0, uint32_t mbar1, int &ph0, int &ph1,
    int tid, int rbase, int colbase, int g, int tig)
{
    float acc[2][8][4];
    #pragma unroll
    for (int m = 0; m < 2; ++m)
        #pragma unroll
        for (int j = 0; j < 8; ++j)
            #pragma unroll
            for (int q = 0; q < 4; ++q) acc[m][j][q] = 0.f;

    if (tid == 0){
        MBAR_EXPECT(mbar0, CHBYTES);
        BULK_G2S(ws0u, Wt, mbar0);
    }
    __syncthreads();   // h writes (stage1 / prev epilogue) visible before A-frag reads

    const uint32_t bbase = (uint32_t)(tig*HDIM + colbase + g);   // word offset in chunk buffer

    for (int c = 0; c < NCH; ++c){
        if (tid == 0 && c + 1 < NCH){
            uint32_t nm  = ((c+1) & 1) ? mbar1 : mbar0;
            uint32_t ndu = ((c+1) & 1) ? ws1u : ws0u;
            MBAR_EXPECT(nm, CHBYTES);
            BULK_G2S(ndu, Wt + (size_t)(c+1)*WSW, nm);
        }
        if (c & 1){ mbar_wait(mbar1, ph1); ph1 ^= 1; }
        else      { mbar_wait(mbar0, ph0); ph0 ^= 1; }
        const float* wsb = (c & 1) ? ws1 : ws0;
        const int kb = c*KCH;

        #pragma unroll
        for (int s = 0; s < 2; ++s){
            uint32_t a[2][4];
            #pragma unroll
            for (int m = 0; m < 2; ++m){
                int r = rbase + m*16 + g;
                int k = kb + 8*s + tig;
                a[m][0] = __float_as_uint(h[r*HP + k]);
                a[m][1] = __float_as_uint(h[(r+8)*HP + k]);
                a[m][2] = __float_as_uint(h[r*HP + k + 4]);
                a[m][3] = __float_as_uint(h[(r+8)*HP + k + 4]);
            }
            #pragma unroll
            for (int j = 0; j < 8; ++j){
                uint32_t off = bbase + 4096u*s + 8u*(uint32_t)(j ^ tig);
                uint32_t b0 = __float_as_uint(wsb[off]);
                uint32_t b1 = __float_as_uint(wsb[off + 4*HDIM]);
                mma_tf32(acc[0][j][0], acc[0][j][1], acc[0][j][2], acc[0][j][3],
                         a[0][0], a[0][1], a[0][2], a[0][3], b0, b1);
                mma_tf32(acc[1][j][0], acc[1][j][1], acc[1][j][2], acc[1][j][3],
                         a[1][0], a[1][1], a[1][2], a[1][3], b0, b1);
            }
        }
        __syncthreads();   // all warps done with this buffer before it is refilled
    }

    // epilogue: h = rna(relu(acc + bias) + h), in place
    #pragma unroll
    for (int m = 0; m < 2; ++m){
        int ra = rbase + m*16 + g;
        int rb = ra + 8;
        #pragma unroll
        for (int j = 0; j < 8; ++j){
            int n0 = colbase + 8*j + 2*tig;
            float bi0 = bias_s[n0], bi1 = bias_s[n0+1];
            float* pa = &h[ra*HP + n0];
            float* pb = &h[rb*HP + n0];
            pa[0] = rna_tf32(fmaxf(acc[m][j][0] + bi0, 0.f) + pa[0]);
            pa[1] = rna_tf32(fmaxf(acc[m][j][1] + bi1, 0.f) + pa[1]);
            pb[0] = rna_tf32(fmaxf(acc[m][j][2] + bi0, 0.f) + pb[0]);
            pb[1] = rna_tf32(fmaxf(acc[m][j][3] + bi1, 0.f) + pb[1]);
        }
    }
    __syncthreads();
}

__global__ __launch_bounds__(NT, 1)
void deform_kernel(const float* __restrict__ x_in, float* __restrict__ x_out,
    const float* __restrict__ W1a, const float* __restrict__ b1a,
    const float* __restrict__ b2a, const float* __restrict__ b3a,
    const float* __restrict__ W4a, const float* __restrict__ b4a,
    const float* __restrict__ W1b, const float* __restrict__ b1b,
    const float* __restrict__ b2b, const float* __restrict__ b3b,
    const float* __restrict__ W4b, const float* __restrict__ b4b)
{
    extern __shared__ char dsm[];
    uintptr_t pa = (reinterpret_cast<uintptr_t>(dsm) + 1023) & ~(uintptr_t)1023;
    float* h   = reinterpret_cast<float*>(pa);        // 64 x 516 fp32
    float* ws0 = h + ROWS*HP;                         // 8192 words
    float* ws1 = ws0 + WSW;                           // 8192 words
    float* msc = ws1 + WSW;                           // 5120 words
    float* sfs  = msc;
    float* b1s  = msc + 512;
    float* b2s  = msc + 1024;
    float* b3s  = msc + 1536;
    float* w1xs = msc + 2048;
    float* w1ys = msc + 2560;
    float* w1zs = msc + 3072;
    float* w4s  = msc + 3584;   // 3*512

    __shared__ __align__(8) unsigned long long mbar_s[2];
    __shared__ float p0[ROWS][3], pe[ROWS][3], ksum[ROWS][3], kcur[ROWS][3];

    const int tid = threadIdx.x;
    const int wid = tid >> 5, lane = tid & 31;
    const int g = lane >> 2, tig = lane & 3;
    const int rbase = (wid & 1) * 32;
    const int colbase = (wid >> 1) * 64;
    const int base = blockIdx.x * ROWS;
    const int b = base >> 12;

    const uint32_t ws0u = smem_u32(ws0), ws1u = smem_u32(ws1);
    const uint32_t mbar0 = smem_u32(&mbar_s[0]), mbar1 = smem_u32(&mbar_s[1]);
    int ph0 = 0, ph1 = 0;

    if (tid == 0){ MBAR_INIT(mbar0, 1); MBAR_INIT(mbar1, 1); }
    if (tid < ROWS*3){
        int r = tid/3, j = tid - r*3;
        float v = x_in[(base + r)*3 + j];
        p0[r][j] = v; pe[r][j] = v;
    }
    __syncthreads();

    const float dt = 0.05f;   // TIME / N_STEPS

    for (int f = 0; f < 2; ++f){
        const float* W1 = f ? W1b : W1a;
        const float* B1 = f ? b1b : b1a;
        const float* B2 = f ? b2b : b2a;
        const float* B3 = f ? b3b : b3a;
        const float* W4 = f ? W4b : W4a;
        const float* B4 = f ? b4b : b4a;
        const float* Wt2 = g_wt[f*2 + 0];
        const float* Wt3 = g_wt[f*2 + 1];

        __syncthreads();
        {
            int c = tid;   // 512 threads = 512 cols
            sfs[c]  = g_sf[f][b][c];
            b1s[c]  = B1[c]; b2s[c] = B2[c]; b3s[c] = B3[c];
            w1xs[c] = W1[c*3+0]; w1ys[c] = W1[c*3+1]; w1zs[c] = W1[c*3+2];
            w4s[c]        = W4[c];
            w4s[512 + c]  = W4[512 + c];
            w4s[1024 + c] = W4[1024 + c];
        }
        __syncthreads();

        for (int step = 0; step < 4; ++step){
            for (int s = 0; s < 4; ++s){
                // ---- stage 1: h = rna(relu(pe @ W1^T + b1) * sf); warp w -> rows 4w..4w+3
                #pragma unroll
                for (int cc = 0; cc < 4; ++cc){
                    int c4 = cc*128 + lane*4;
                    float4 wx = *reinterpret_cast<const float4*>(&w1xs[c4]);
                    float4 wy = *reinterpret_cast<const float4*>(&w1ys[c4]);
                    float4 wz = *reinterpret_cast<const float4*>(&w1zs[c4]);
                    float4 bb = *reinterpret_cast<const float4*>(&b1s[c4]);
                    float4 sf4 = *reinterpret_cast<const float4*>(&sfs[c4]);
                    #pragma unroll
                    for (int rr = 0; rr < 4; ++rr){
                        int r = wid*4 + rr;
                        float px = pe[r][0], py = pe[r][1], pz = pe[r][2];
                        float4 o;
                        o.x = rna_tf32(fmaxf(fmaf(px, wx.x, fmaf(py, wy.x, fmaf(pz, wz.x, bb.x))), 0.f) * sf4.x);
                        o.y = rna_tf32(fmaxf(fmaf(px, wx.y, fmaf(py, wy.y, fmaf(pz, wz.y, bb.y))), 0.f) * sf4.y);
                        o.z = rna_tf32(fmaxf(fmaf(px, wx.z, fmaf(py, wy.z, fmaf(pz, wz.z, bb.z))), 0.f) * sf4.z);
                        o.w = rna_tf32(fmaxf(fmaf(px, wx.w, fmaf(py, wy.w, fmaf(pz, wz.w, bb.w))), 0.f) * sf4.w);
                        *reinterpret_cast<float4*>(&h[r*HP + c4]) = o;
                    }
                }
                // (gemm_res's leading __syncthreads publishes h)

                gemm_res(h, ws0, ws1, ws0u, ws1u, Wt2, b2s, mbar0, mbar1, ph0, ph1, tid, rbase, colbase, g, tig);
                gemm_res(h, ws0, ws1, ws0u, ws1u, Wt3, b3s, mbar0, mbar1, ph0, ph1, tid, rbase, colbase, g, tig);

                // ---- stage 4: kcur = tanh(h @ W4^T + b4); warp w -> rows 4w..4w+3
                {
                    float a[4][3];
                    #pragma unroll
                    for (int rr = 0; rr < 4; ++rr){ a[rr][0]=0.f; a[rr][1]=0.f; a[rr][2]=0.f; }
                    #pragma unroll 2
                    for (int i = 0; i < 16; ++i){
                        int k = lane + i*32;
                        float w0 = w4s[k], w1 = w4s[512+k], w2 = w4s[1024+k];
                        #pragma unroll
                        for (int rr = 0; rr < 4; ++rr){
                            float hv = h[(wid*4 + rr)*HP + k];
                            a[rr][0] = fmaf(hv, w0, a[rr][0]);
                            a[rr][1] = fmaf(hv, w1, a[rr][1]);
                            a[rr][2] = fmaf(hv, w2, a[rr][2]);
                        }
                    }
                    #pragma unroll
                    for (int rr = 0; rr < 4; ++rr){
                        #pragma unroll
                        for (int j = 0; j < 3; ++j){
                            float v = a[rr][j];
                            #pragma unroll
                            for (int off = 16; off > 0; off >>= 1)
                                v += __shfl_xor_sync(0xffffffffu, v, off);
                            if (lane == 0) kcur[wid*4 + rr][j] = tanhf(v + B4[j]);
                        }
                    }
                }
                __syncthreads();

                // ---- RK4 state update
                if (tid < ROWS*3){
                    int r = tid/3, j = tid - r*3;
                    float k = kcur[r][j];
                    if (s == 0){ ksum[r][j] = k;            pe[r][j] = fmaf(0.5f*dt, k, p0[r][j]); }
                    else if (s == 1){ ksum[r][j] += 2.f*k;  pe[r][j] = fmaf(0.5f*dt, k, p0[r][j]); }
                    else if (s == 2){ ksum[r][j] += 2.f*k;  pe[r][j] = fmaf(dt, k, p0[r][j]); }
                    else { float p = fmaf(dt/6.f, ksum[r][j] + k, p0[r][j]); p0[r][j] = p; pe[r][j] = p; }
                }
                __syncthreads();
            }
        }
    }

    if (tid < ROWS*3){
        int r = tid/3, j = tid - r*3;
        x_out[(base + r)*3 + j] = p0[r][j];
    }
    __syncthreads();
    if (tid == 0){ MBAR_INVAL(mbar0); MBAR_INVAL(mbar1); }
}

extern "C" void kernel_launch(void* const* d_in, const int* in_sizes, int n_in,
                              void* d_out, int out_size)
{
    const float* code   = (const float*)d_in[0];
    const float* x      = (const float*)d_in[1];
    const float* f1_l1w = (const float*)d_in[2];
    const float* f1_l1b = (const float*)d_in[3];
    const float* f1_l2w = (const float*)d_in[4];
    const float* f1_l2b = (const float*)d_in[5];
    const float* f1_l3w = (const float*)d_in[6];
    const float* f1_l3b = (const float*)d_in[7];
    const float* f1_l4w = (const float*)d_in[8];
    const float* f1_l4b = (const float*)d_in[9];
    const float* f1_cw  = (const float*)d_in[10];
    const float* f1_cb  = (const float*)d_in[11];
    const float* f2_l1w = (const float*)d_in[12];
    const float* f2_l1b = (const float*)d_in[13];
    const float* f2_l2w = (const float*)d_in[14];
    const float* f2_l2b = (const float*)d_in[15];
    const float* f2_l3w = (const float*)d_in[16];
    const float* f2_l3b = (const float*)d_in[17];
    const float* f2_l4w = (const float*)d_in[18];
    const float* f2_l4b = (const float*)d_in[19];
    const float* f2_cw  = (const float*)d_in[20];
    const float* f2_cb  = (const float*)d_in[21];
    float* out = (float*)d_out;

    const int smem_bytes = 1024 + (ROWS*HP + 2*WSW + 5120) * (int)sizeof(float);  // ~219 KB
    cudaFuncSetAttribute(deform_kernel, cudaFuncAttributeMaxDynamicSharedMemorySize, smem_bytes);

    prep_kernel<<<dim3(16, 16, 4), dim3(32, 8)>>>(f1_l2w, f1_l3w, f2_l2w, f2_l3w);
    sf_kernel<<<dim3(4, 2), HDIM>>>(code, f1_cw, f1_cb, f2_cw, f2_cb);

    const int n_blocks = (4 * 4096) / ROWS;  // 256
    deform_kernel<<<n_blocks, NT, smem_bytes>>>(
        x, out,
        f1_l1w, f1_l1b, f1_l2b, f1_l3b, f1_l4w, f1_l4b,
        f2_l1w, f2_l1b, f2_l2b, f2_l3b, f2_l4w, f2_l4b);
}

// round 8
// speedup vs baseline: 12.1552x; 2.4192x over previous
#include <cuda_runtime.h>
#include <cuda_bf16.h>
#include <cstdint>

#define HDIM 512
#define ROWS 64          // rows per CTA
#define NT   512         // 16 warps
#define HBS  520         // hb row stride in bf16 elements (1040 B) -> conflict-free ldmatrix A
#define KCH  32          // K per chunk
#define NCH  16          // 512/32 chunks
#define WKP  40          // padded k-extent per W chunk row (80 B) -> conflict-free ldmatrix B
#define CHBYTES (512*WKP*2)   // 40960 B per W chunk

__device__ float g_sf[2][4][HDIM];
// bf16 W2/W3 (f1,f2), chunked [mat][chunk][n][WKP]
__device__ __align__(16) __nv_bfloat16 g_wb[4][NCH*512*WKP];

// ---------------- helpers ----------------
__device__ __forceinline__ uint32_t smem_u32(const void* p){
    uint32_t a;
    asm("{ .reg .u64 t; cvta.to.shared.u64 t, %1; cvt.u32.u64 %0, t; }" : "=r"(a) : "l"(p));
    return a;
}
__device__ __forceinline__ void mbar_wait(uint32_t mbar, int parity){
    asm volatile(
        "{\n\t.reg .pred P;\n\t"
        "LAB%=:\n\t"
        "mbarrier.try_wait.parity.acquire.cta.shared::cta.b64 P, [%0], %1, 0x989680;\n\t"
        "@!P bra LAB%=;\n\t}"
        :: "r"(mbar), "r"(parity) : "memory");
}
#define MBAR_INIT(a, c)   asm volatile("mbarrier.init.shared.b64 [%0], %1;" :: "r"(a), "r"((uint32_t)(c)) : "memory")
#define MBAR_INVAL(a)     asm volatile("mbarrier.inval.shared.b64 [%0];" :: "r"(a) : "memory")
#define MBAR_EXPECT(a, b) asm volatile("mbarrier.arrive.expect_tx.shared.b64 _, [%0], %1;" :: "r"(a), "r"((uint32_t)(b)) : "memory")
#define BULK_G2S(dst, src, mbar) \
    asm volatile("cp.async.bulk.shared::cluster.global.mbarrier::complete_tx::bytes [%0], [%1], %2, [%3];" \
        :: "r"(dst), "l"(src), "r"((uint32_t)CHBYTES), "r"(mbar) : "memory")
#define LDMX4(r, addr) \
    asm volatile("ldmatrix.sync.aligned.m8n8.x4.shared.b16 {%0,%1,%2,%3}, [%4];" \
        : "=r"((r)[0]), "=r"((r)[1]), "=r"((r)[2]), "=r"((r)[3]) : "r"(addr))
#define MMA_BF16(d, a, b0, b1) \
    asm volatile("mma.sync.aligned.m16n8k16.row.col.f32.bf16.bf16.f32 " \
        "{%0,%1,%2,%3}, {%4,%5,%6,%7}, {%8,%9}, {%0,%1,%2,%3};" \
        : "+f"((d)[0]), "+f"((d)[1]), "+f"((d)[2]), "+f"((d)[3]) \
        : "r"((a)[0]), "r"((a)[1]), "r"((a)[2]), "r"((a)[3]), "r"(b0), "r"(b1))

// ---------------- prep: pack W2/W3 as bf16 chunks, padded rows ----------------
__global__ void prep_w(const float* __restrict__ W2a, const float* __restrict__ W3a,
                       const float* __restrict__ W2b, const float* __restrict__ W3b){
    int mat = blockIdx.y;
    const float* W = mat==0 ? W2a : mat==1 ? W3a : mat==2 ? W2b : W3b;
    int c = blockIdx.x;                    // chunk
    int kk = threadIdx.x & 31;
    int ns = threadIdx.x >> 5;             // 0..15
    for (int n = ns; n < 512; n += 16){
        float v = W[n*HDIM + c*KCH + kk];
        g_wb[mat][(c*512 + n)*WKP + kk] = __float2bfloat16_rn(v);
    }
}

// sf[f][b][:] = tanh(code[b] @ cond_w^T + cond_b)
__global__ void sf_kernel(const float* __restrict__ code,
                          const float* __restrict__ cw1, const float* __restrict__ cb1,
                          const float* __restrict__ cw2, const float* __restrict__ cb2){
    int b = blockIdx.x, f = blockIdx.y, t = threadIdx.x;
    const float* cw = f ? cw2 : cw1;
    const float* cb = f ? cb2 : cb1;
    const float4* c4 = reinterpret_cast<const float4*>(code + b*HDIM);
    const float4* w4 = reinterpret_cast<const float4*>(cw + t*HDIM);
    float s = 0.f;
    #pragma unroll 4
    for (int i = 0; i < HDIM/4; i++){
        float4 a = c4[i], w = w4[i];
        s = fmaf(a.x, w.x, fmaf(a.y, w.y, fmaf(a.z, w.z, fmaf(a.w, w.w, s))));
    }
    g_sf[f][b][t] = tanhf(s + cb[t]);
}

// one residual stage: h = relu(h @ W^T + bias) + h via bf16 mma.sync + ldmatrix
__device__ __forceinline__ void gemm_res(
    uint32_t* __restrict__ hb2, uint32_t hb_u32,
    uint32_t wc0u, uint32_t wc1u,
    const __nv_bfloat16* __restrict__ Wc, const float* __restrict__ bias_s,
    uint32_t mbar0, uint32_t mbar1, int &ph0, int &ph1,
    int tid, int lane, int rbase, int colbase)
{
    const int g = lane >> 2, tig = lane & 3;
    // ldmatrix lane-address components
    const uint32_t a_lrow = (uint32_t)((lane & 7) + ((lane & 8) ? 8 : 0));      // row within m16
    const uint32_t a_koff = (lane & 16) ? 8u : 0u;
    const uint32_t b_lrow = (uint32_t)((lane & 7) + ((lane & 16) ? 8 : 0));     // n within 16
    const uint32_t b_koff = (lane & 8) ? 8u : 0u;

    float acc[2][8][4];
    #pragma unroll
    for (int m = 0; m < 2; ++m)
        #pragma unroll
        for (int j = 0; j < 8; ++j)
            #pragma unroll
            for (int q = 0; q < 4; ++q) acc[m][j][q] = 0.f;

    if (tid == 0){
        MBAR_EXPECT(mbar0, CHBYTES);
        BULK_G2S(wc0u, Wc, mbar0);
    }
    __syncthreads();   // publishes hb writes (stage1 / prev epilogue) before A-frag reads

    for (int c = 0; c < NCH; ++c){
        if (tid == 0 && c + 1 < NCH){
            uint32_t nm  = ((c+1) & 1) ? mbar1 : mbar0;
            uint32_t ndu = ((c+1) & 1) ? wc1u : wc0u;
            MBAR_EXPECT(nm, CHBYTES);
            BULK_G2S(ndu, Wc + (size_t)(c+1)*512*WKP, nm);
        }
        if (c & 1){ mbar_wait(mbar1, ph1); ph1 ^= 1; }
        else      { mbar_wait(mbar0, ph0); ph0 ^= 1; }
        const uint32_t wcu = (c & 1) ? wc1u : wc0u;

        // A fragments for this chunk: [m][s][4]
        uint32_t Afr[2][2][4];
        #pragma unroll
        for (int m = 0; m < 2; ++m)
            #pragma unroll
            for (int s = 0; s < 2; ++s){
                uint32_t addr = hb_u32 +
                    (((uint32_t)(rbase + 16*m) + a_lrow)*HBS + (uint32_t)(c*KCH + s*16) + a_koff)*2u;
                LDMX4(Afr[m][s], addr);
            }

        #pragma unroll
        for (int s = 0; s < 2; ++s){
            #pragma unroll
            for (int jj = 0; jj < 4; ++jj){
                uint32_t B[4];
                uint32_t addr = wcu +
                    (((uint32_t)(colbase + 16*jj) + b_lrow)*WKP + (uint32_t)(s*16) + b_koff)*2u;
                LDMX4(B, addr);
                MMA_BF16(acc[0][2*jj],   Afr[0][s], B[0], B[1]);
                MMA_BF16(acc[0][2*jj+1], Afr[0][s], B[2], B[3]);
                MMA_BF16(acc[1][2*jj],   Afr[1][s], B[0], B[1]);
                MMA_BF16(acc[1][2*jj+1], Afr[1][s], B[2], B[3]);
            }
        }
        __syncthreads();   // all warps done with this buffer before refill
    }

    // epilogue: h = bf16(relu(acc + bias) + h), in place
    #pragma unroll
    for (int m = 0; m < 2; ++m){
        int r = rbase + 16*m + g;
        #pragma unroll
        for (int j = 0; j < 8; ++j){
            int cc = colbase + 8*j + 2*tig;
            float bi0 = bias_s[cc], bi1 = bias_s[cc+1];
            #pragma unroll
            for (int hh = 0; hh < 2; ++hh){            // hh=0: row r (d0,d1); hh=1: row r+8 (d2,d3)
                uint32_t* hp = &hb2[(r + 8*hh)*(HBS/2) + (cc >> 1)];
                __nv_bfloat162 old = *reinterpret_cast<__nv_bfloat162*>(hp);
                float nx = fmaxf(acc[m][j][2*hh]   + bi0, 0.f) + __bfloat162float(old.x);
                float ny = fmaxf(acc[m][j][2*hh+1] + bi1, 0.f) + __bfloat162float(old.y);
                __nv_bfloat162 nv = __floats2bfloat162_rn(nx, ny);
                *hp = *reinterpret_cast<uint32_t*>(&nv);
            }
        }
    }
    __syncthreads();
}

__global__ __launch_bounds__(NT, 1)
void deform_kernel(const float* __restrict__ x_in, float* __restrict__ x_out,
    const float* __restrict__ W1a, const float* __restrict__ b1a,
    const float* __restrict__ b2a, const float* __restrict__ b3a,
    const float* __restrict__ W4a, const float* __restrict__ b4a,
    const float* __restrict__ W1b, const float* __restrict__ b1b,
    const float* __restrict__ b2b, const float* __restrict__ b3b,
    const float* __restrict__ W4b, const float* __restrict__ b4b)
{
    extern __shared__ char dsm[];
    uintptr_t pa = (reinterpret_cast<uintptr_t>(dsm) + 1023) & ~(uintptr_t)1023;
    char* hb  = reinterpret_cast<char*>(pa);            // 64 x 520 bf16 = 66560 B
    char* wc0 = hb + ROWS*HBS*2;                        // 40960 B
    char* wc1 = wc0 + CHBYTES;                          // 40960 B
    float* msc = reinterpret_cast<float*>(wc1 + CHBYTES);
    float* sfs  = msc;
    float* b1s  = msc + 512;
    float* b2s  = msc + 1024;
    float* b3s  = msc + 1536;
    float* w1xs = msc + 2048;
    float* w1ys = msc + 2560;
    float* w1zs = msc + 3072;
    float* w4s  = msc + 3584;   // 3*512

    uint32_t* hb2 = reinterpret_cast<uint32_t*>(hb);    // bf16-pair view, stride HBS/2

    __shared__ __align__(8) unsigned long long mbar_s[2];
    __shared__ float p0[ROWS][3], pe[ROWS][3], ksum[ROWS][3], kcur[ROWS][3];

    const int tid = threadIdx.x;
    const int wid = tid >> 5, lane = tid & 31;
    const int rbase = (wid & 1) * 32;
    const int colbase = (wid >> 1) * 64;
    const int base = blockIdx.x * ROWS;
    const int b = base >> 12;

    const uint32_t hb_u32 = smem_u32(hb);
    const uint32_t wc0u = smem_u32(wc0), wc1u = smem_u32(wc1);
    const uint32_t mbar0 = smem_u32(&mbar_s[0]), mbar1 = smem_u32(&mbar_s[1]);
    int ph0 = 0, ph1 = 0;

    if (tid == 0){ MBAR_INIT(mbar0, 1); MBAR_INIT(mbar1, 1); }
    if (tid < ROWS*3){
        int r = tid/3, j = tid - r*3;
        float v = x_in[(base + r)*3 + j];
        p0[r][j] = v; pe[r][j] = v;
    }
    __syncthreads();

    const float dt = 0.05f;   // TIME / N_STEPS

    for (int f = 0; f < 2; ++f){
        const float* W1 = f ? W1b : W1a;
        const float* B1 = f ? b1b : b1a;
        const float* B2 = f ? b2b : b2a;
        const float* B3 = f ? b3b : b3a;
        const float* W4 = f ? W4b : W4a;
        const float* B4 = f ? b4b : b4a;
        const __nv_bfloat16* Wc2 = g_wb[f*2 + 0];
        const __nv_bfloat16* Wc3 = g_wb[f*2 + 1];

        __syncthreads();
        {
            int c = tid;
            sfs[c]  = g_sf[f][b][c];
            b1s[c]  = B1[c]; b2s[c] = B2[c]; b3s[c] = B3[c];
            w1xs[c] = W1[c*3+0]; w1ys[c] = W1[c*3+1]; w1zs[c] = W1[c*3+2];
            w4s[c]        = W4[c];
            w4s[512 + c]  = W4[512 + c];
            w4s[1024 + c] = W4[1024 + c];
        }
        __syncthreads();

        for (int step = 0; step < 4; ++step){
            for (int s = 0; s < 4; ++s){
                // ---- stage 1: h = bf16(relu(pe @ W1^T + b1) * sf); warp w -> rows 4w..4w+3
                #pragma unroll
                for (int cc = 0; cc < 4; ++cc){
                    int c4 = cc*128 + lane*4;
                    float4 wx = *reinterpret_cast<const float4*>(&w1xs[c4]);
                    float4 wy = *reinterpret_cast<const float4*>(&w1ys[c4]);
                    float4 wz = *reinterpret_cast<const float4*>(&w1zs[c4]);
                    float4 bb = *reinterpret_cast<const float4*>(&b1s[c4]);
                    float4 sf4 = *reinterpret_cast<const float4*>(&sfs[c4]);
                    #pragma unroll
                    for (int rr = 0; rr < 4; ++rr){
                        int r = wid*4 + rr;
                        float px = pe[r][0], py = pe[r][1], pz = pe[r][2];
                        float ox = fmaxf(fmaf(px, wx.x, fmaf(py, wy.x, fmaf(pz, wz.x, bb.x))), 0.f) * sf4.x;
                        float oy = fmaxf(fmaf(px, wx.y, fmaf(py, wy.y, fmaf(pz, wz.y, bb.y))), 0.f) * sf4.y;
                        float oz = fmaxf(fmaf(px, wx.z, fmaf(py, wy.z, fmaf(pz, wz.z, bb.z))), 0.f) * sf4.z;
                        float ow = fmaxf(fmaf(px, wx.w, fmaf(py, wy.w, fmaf(pz, wz.w, bb.w))), 0.f) * sf4.w;
                        __nv_bfloat162 pA = __floats2bfloat162_rn(ox, oy);
                        __nv_bfloat162 pB = __floats2bfloat162_rn(oz, ow);
                        uint2 pk = make_uint2(*reinterpret_cast<uint32_t*>(&pA),
                                              *reinterpret_cast<uint32_t*>(&pB));
                        *reinterpret_cast<uint2*>(&hb2[r*(HBS/2) + (c4 >> 1)]) = pk;
                    }
                }
                // (gemm_res's leading __syncthreads publishes hb)

                gemm_res(hb2, hb_u32, wc0u, wc1u, Wc2, b2s, mbar0, mbar1, ph0, ph1, tid, lane, rbase, colbase);
                gemm_res(hb2, hb_u32, wc0u, wc1u, Wc3, b3s, mbar0, mbar1, ph0, ph1, tid, lane, rbase, colbase);

                // ---- stage 4: kcur = tanh(h @ W4^T + b4); warp w -> rows 4w..4w+3
                {
                    float a[4][3];
                    #pragma unroll
                    for (int rr = 0; rr < 4; ++rr){ a[rr][0]=0.f; a[rr][1]=0.f; a[rr][2]=0.f; }
                    #pragma unroll 2
                    for (int i = 0; i < 8; ++i){
                        int idx = lane + i*32;          // bf16-pair index: k = 2idx, 2idx+1
                        float w00 = w4s[2*idx],        w01 = w4s[2*idx+1];
                        float w10 = w4s[512 + 2*idx],  w11 = w4s[512 + 2*idx+1];
                        float w20 = w4s[1024 + 2*idx], w21 = w4s[1024 + 2*idx+1];
                        #pragma unroll
                        for (int rr = 0; rr < 4; ++rr){
                            uint32_t pv = hb2[(wid*4 + rr)*(HBS/2) + idx];
                            __nv_bfloat162 hv = *reinterpret_cast<__nv_bfloat162*>(&pv);
                            float hx = __bfloat162float(hv.x), hy = __bfloat162float(hv.y);
                            a[rr][0] = fmaf(hx, w00, fmaf(hy, w01, a[rr][0]));
                            a[rr][1] = fmaf(hx, w10, fmaf(hy, w11, a[rr][1]));
                            a[rr][2] = fmaf(hx, w20, fmaf(hy, w21, a[rr][2]));
                        }
                    }
                    #pragma unroll
                    for (int rr = 0; rr < 4; ++rr){
                        #pragma unroll
                        for (int j = 0; j < 3; ++j){
                            float v = a[rr][j];
                            #pragma unroll
                            for (int off = 16; off > 0; off >>= 1)
                                v += __shfl_xor_sync(0xffffffffu, v, off);
                            if (lane == 0) kcur[wid*4 + rr][j] = tanhf(v + B4[j]);
                        }
                    }
                }
                __syncthreads();

                // ---- RK4 state update
                if (tid < ROWS*3){
                    int r = tid/3, j = tid - r*3;
                    float k = kcur[r][j];
                    if (s == 0){ ksum[r][j] = k;            pe[r][j] = fmaf(0.5f*dt, k, p0[r][j]); }
                    else if (s == 1){ ksum[r][j] += 2.f*k;  pe[r][j] = fmaf(0.5f*dt, k, p0[r][j]); }
                    else if (s == 2){ ksum[r][j] += 2.f*k;  pe[r][j] = fmaf(dt, k, p0[r][j]); }
                    else { float p = fmaf(dt/6.f, ksum[r][j] + k, p0[r][j]); p0[r][j] = p; pe[r][j] = p; }
                }
                __syncthreads();
            }
        }
    }

    if (tid < ROWS*3){
        int r = tid/3, j = tid - r*3;
        x_out[(base + r)*3 + j] = p0[r][j];
    }
    __syncthreads();
    if (tid == 0){ MBAR_INVAL(mbar0); MBAR_INVAL(mbar1); }
}

extern "C" void kernel_launch(void* const* d_in, const int* in_sizes, int n_in,
                              void* d_out, int out_size)
{
    const float* code   = (const float*)d_in[0];
    const float* x      = (const float*)d_in[1];
    const float* f1_l1w = (const float*)d_in[2];
    const float* f1_l1b = (const float*)d_in[3];
    const float* f1_l2w = (const float*)d_in[4];
    const float* f1_l2b = (const float*)d_in[5];
    const float* f1_l3w = (const float*)d_in[6];
    const float* f1_l3b = (const float*)d_in[7];
    const float* f1_l4w = (const float*)d_in[8];
    const float* f1_l4b = (const float*)d_in[9];
    const float* f1_cw  = (const float*)d_in[10];
    const float* f1_cb  = (const float*)d_in[11];
    const float* f2_l1w = (const float*)d_in[12];
    const float* f2_l1b = (const float*)d_in[13];
    const float* f2_l2w = (const float*)d_in[14];
    const float* f2_l2b = (const float*)d_in[15];
    const float* f2_l3w = (const float*)d_in[16];
    const float* f2_l3b = (const float*)d_in[17];
    const float* f2_l4w = (const float*)d_in[18];
    const float* f2_l4b = (const float*)d_in[19];
    const float* f2_cw  = (const float*)d_in[20];
    const float* f2_cb  = (const float*)d_in[21];
    float* out = (float*)d_out;

    const int smem_bytes = 1024 + ROWS*HBS*2 + 2*CHBYTES + 5120*4;   // ~170 KB
    cudaFuncSetAttribute(deform_kernel, cudaFuncAttributeMaxDynamicSharedMemorySize, smem_bytes);

    prep_w<<<dim3(NCH, 4), NT>>>(f1_l2w, f1_l3w, f2_l2w, f2_l3w);
    sf_kernel<<<dim3(4, 2), HDIM>>>(code, f1_cw, f1_cb, f2_cw, f2_cb);

    const int n_blocks = (4 * 4096) / ROWS;  // 256
    deform_kernel<<<n_blocks, NT, smem_bytes>>>(
        x, out,
        f1_l1w, f1_l1b, f1_l2b, f1_l3b, f1_l4w, f1_l4b,
        f2_l1w, f2_l1b, f2_l2b, f2_l3b, f2_l4w, f2_l4b);
}

// round 9
// speedup vs baseline: 12.9433x; 1.0648x over previous
#include <cuda_runtime.h>
#include <cuda_bf16.h>
#include <cstdint>

#define HDIM 512
#define ROWS 64          // rows per CTA
#define NT   512         // 16 warps
#define HBS  520         // hb row stride in bf16 elements (1040 B) -> conflict-free ldmatrix A
#define KCH  32          // K per chunk
#define NCH  16          // chunks per GEMM
#define WKP  40          // padded k-extent per W chunk row (80 B) -> conflict-free ldmatrix B
#define CHW  (512*WKP)        // elements per W chunk
#define CHBYTES (CHW*2)       // 40960 B per W chunk
#define NBUF 3

__device__ float g_sf[2][4][HDIM];
// bf16 W2/W3 (f1,f2), chunked [mat][chunk][n][WKP]
__device__ __align__(16) __nv_bfloat16 g_wb[4][NCH*CHW];

// ---------------- helpers ----------------
__device__ __forceinline__ uint32_t smem_u32(const void* p){
    uint32_t a;
    asm("{ .reg .u64 t; cvta.to.shared.u64 t, %1; cvt.u32.u64 %0, t; }" : "=r"(a) : "l"(p));
    return a;
}
__device__ __forceinline__ void mbar_wait(uint32_t mbar, uint32_t parity){
    asm volatile(
        "{\n\t.reg .pred P;\n\t"
        "LAB%=:\n\t"
        "mbarrier.try_wait.parity.acquire.cta.shared::cta.b64 P, [%0], %1, 0x989680;\n\t"
        "@!P bra LAB%=;\n\t}"
        :: "r"(mbar), "r"(parity) : "memory");
}
#define MBAR_INIT(a, c)   asm volatile("mbarrier.init.shared.b64 [%0], %1;" :: "r"(a), "r"((uint32_t)(c)) : "memory")
#define MBAR_INVAL(a)     asm volatile("mbarrier.inval.shared.b64 [%0];" :: "r"(a) : "memory")
#define MBAR_EXPECT(a, b) asm volatile("mbarrier.arrive.expect_tx.shared.b64 _, [%0], %1;" :: "r"(a), "r"((uint32_t)(b)) : "memory")
#define MBAR_ARRIVE(a)    asm volatile("mbarrier.arrive.shared.b64 _, [%0];" :: "r"(a) : "memory")
#define BULK_G2S(dst, src, mbar) \
    asm volatile("cp.async.bulk.shared::cluster.global.mbarrier::complete_tx::bytes [%0], [%1], %2, [%3];" \
        :: "r"(dst), "l"(src), "r"((uint32_t)CHBYTES), "r"(mbar) : "memory")
#define LDMX4(r, addr) \
    asm volatile("ldmatrix.sync.aligned.m8n8.x4.shared.b16 {%0,%1,%2,%3}, [%4];" \
        : "=r"((r)[0]), "=r"((r)[1]), "=r"((r)[2]), "=r"((r)[3]) : "r"(addr))
#define MMA_BF16(d, a, b0, b1) \
    asm volatile("mma.sync.aligned.m16n8k16.row.col.f32.bf16.bf16.f32 " \
        "{%0,%1,%2,%3}, {%4,%5,%6,%7}, {%8,%9}, {%0,%1,%2,%3};" \
        : "+f"((d)[0]), "+f"((d)[1]), "+f"((d)[2]), "+f"((d)[3]) \
        : "r"((a)[0]), "r"((a)[1]), "r"((a)[2]), "r"((a)[3]), "r"(b0), "r"(b1))

// ---------------- prep: pack W2/W3 as bf16 chunks, padded rows ----------------
__global__ void prep_w(const float* __restrict__ W2a, const float* __restrict__ W3a,
                       const float* __restrict__ W2b, const float* __restrict__ W3b){
    int mat = blockIdx.y;
    const float* W = mat==0 ? W2a : mat==1 ? W3a : mat==2 ? W2b : W3b;
    int c = blockIdx.x;                    // chunk
    int kk = threadIdx.x & 31;
    int ns = threadIdx.x >> 5;             // 0..15
    for (int n = ns; n < 512; n += 16){
        float v = W[n*HDIM + c*KCH + kk];
        g_wb[mat][(c*512 + n)*WKP + kk] = __float2bfloat16_rn(v);
    }
}

// sf[f][b][:] = tanh(code[b] @ cond_w^T + cond_b)
__global__ void sf_kernel(const float* __restrict__ code,
                          const float* __restrict__ cw1, const float* __restrict__ cb1,
                          const float* __restrict__ cw2, const float* __restrict__ cb2){
    int b = blockIdx.x, f = blockIdx.y, t = threadIdx.x;
    const float* cw = f ? cw2 : cw1;
    const float* cb = f ? cb2 : cb1;
    const float4* c4 = reinterpret_cast<const float4*>(code + b*HDIM);
    const float4* w4 = reinterpret_cast<const float4*>(cw + t*HDIM);
    float s = 0.f;
    #pragma unroll 4
    for (int i = 0; i < HDIM/4; i++){
        float4 a = c4[i], w = w4[i];
        s = fmaf(a.x, w.x, fmaf(a.y, w.y, fmaf(a.z, w.z, fmaf(a.w, w.w, s))));
    }
    g_sf[f][b][t] = tanhf(s + cb[t]);
}

__global__ __launch_bounds__(NT, 1)
void deform_kernel(const float* __restrict__ x_in, float* __restrict__ x_out,
    const float* __restrict__ W1a, const float* __restrict__ b1a,
    const float* __restrict__ b2a, const float* __restrict__ b3a,
    const float* __restrict__ W4a, const float* __restrict__ b4a,
    const float* __restrict__ W1b, const float* __restrict__ b1b,
    const float* __restrict__ b2b, const float* __restrict__ b3b,
    const float* __restrict__ W4b, const float* __restrict__ b4b)
{
    extern __shared__ char dsm[];
    uintptr_t pa = (reinterpret_cast<uintptr_t>(dsm) + 1023) & ~(uintptr_t)1023;
    char* hb  = reinterpret_cast<char*>(pa);            // 64 x 520 bf16 = 66560 B
    char* wc  = hb + ROWS*HBS*2;                        // 3 x 40960 B
    float* msc = reinterpret_cast<float*>(wc + NBUF*CHBYTES);
    float* sfs  = msc;
    float* b1s  = msc + 512;
    float* b2s  = msc + 1024;
    float* b3s  = msc + 1536;
    float* w1xs = msc + 2048;
    float* w1ys = msc + 2560;
    float* w1zs = msc + 3072;
    float* w4s  = msc + 3584;   // 3*512

    uint32_t* hb2 = reinterpret_cast<uint32_t*>(hb);    // bf16-pair view, stride HBS/2

    __shared__ __align__(8) unsigned long long mbarF_s[NBUF], mbarE_s[NBUF];
    __shared__ float p0[ROWS][3], pe[ROWS][3], ksum[ROWS][3], kcur[ROWS][3];

    const int tid = threadIdx.x;
    const int wid = tid >> 5, lane = tid & 31;
    const int g = lane >> 2, tig = lane & 3;
    const int rbase = (wid & 1) * 32;
    const int colbase = (wid >> 1) * 64;
    const int base = blockIdx.x * ROWS;
    const int b = base >> 12;

    const uint32_t hb_u32 = smem_u32(hb);
    const uint32_t wc_u32 = smem_u32(wc);
    const uint32_t mbarF = smem_u32(&mbarF_s[0]);
    const uint32_t mbarE = smem_u32(&mbarE_s[0]);

    // ldmatrix lane-address components
    const uint32_t a_lrow = (uint32_t)(lane & 15);
    const uint32_t a_koff = (lane & 16) ? 8u : 0u;
    const uint32_t b_lrow = (uint32_t)((lane & 7) + ((lane & 16) ? 8 : 0));
    const uint32_t b_koff = (lane & 8) ? 8u : 0u;

    if (tid == 0){
        #pragma unroll
        for (int j = 0; j < NBUF; ++j){
            MBAR_INIT(mbarF + j*8, 1);
            MBAR_INIT(mbarE + j*8, 16);   // one arrive per warp
        }
    }
    if (tid < ROWS*3){
        int r = tid/3, j = tid - r*3;
        float v = x_in[(base + r)*3 + j];
        p0[r][j] = v; pe[r][j] = v;
    }
    __syncthreads();

    uint32_t gb = 0;          // global chunk counter (buffer rotation)
    uint32_t cful = 0;        // consumer full-parity bits per buffer
    uint32_t pemp = 0x7;      // producer empty-parity bits (start 1 -> first wait passes)

    const float dt = 0.05f;   // TIME / N_STEPS

    for (int f = 0; f < 2; ++f){
        const float* W1 = f ? W1b : W1a;
        const float* B1 = f ? b1b : b1a;
        const float* B2 = f ? b2b : b2a;
        const float* B3 = f ? b3b : b3a;
        const float* W4 = f ? W4b : W4a;
        const float* B4 = f ? b4b : b4a;
        const __nv_bfloat16* Wc2 = g_wb[f*2 + 0];
        const __nv_bfloat16* Wc3 = g_wb[f*2 + 1];

        __syncthreads();
        {
            int c = tid;
            sfs[c]  = g_sf[f][b][c];
            b1s[c]  = B1[c]; b2s[c] = B2[c]; b3s[c] = B3[c];
            w1xs[c] = W1[c*3+0]; w1ys[c] = W1[c*3+1]; w1zs[c] = W1[c*3+2];
            w4s[c]        = W4[c];
            w4s[512 + c]  = W4[512 + c];
            w4s[1024 + c] = W4[1024 + c];
        }
        __syncthreads();

        // producer: issue chunk t (0..31 within current eval) into buffer (gb+t)%3
        auto issue = [&](int t){
            uint32_t j = (gb + (uint32_t)t) % NBUF;
            mbar_wait(mbarE + j*8, (pemp >> j) & 1u);
            pemp ^= (1u << j);
            MBAR_EXPECT(mbarF + j*8, CHBYTES);
            const __nv_bfloat16* src = (t < NCH) ? (Wc2 + (size_t)t*CHW)
                                                 : (Wc3 + (size_t)(t - NCH)*CHW);
            BULK_G2S(wc_u32 + j*CHBYTES, src, mbarF + j*8);
        };

        for (int step = 0; step < 4; ++step){
            for (int s = 0; s < 4; ++s){
                // ---- producer prologue: 2 chunks in flight before stage1 compute
                if (tid == 0){ issue(0); issue(1); }

                // ---- stage 1: h = bf16(relu(pe @ W1^T + b1) * sf); warp w -> rows 4w..4w+3
                #pragma unroll
                for (int cc = 0; cc < 4; ++cc){
                    int c4 = cc*128 + lane*4;
                    float4 wx = *reinterpret_cast<const float4*>(&w1xs[c4]);
                    float4 wy = *reinterpret_cast<const float4*>(&w1ys[c4]);
                    float4 wz = *reinterpret_cast<const float4*>(&w1zs[c4]);
                    float4 bb = *reinterpret_cast<const float4*>(&b1s[c4]);
                    float4 sf4 = *reinterpret_cast<const float4*>(&sfs[c4]);
                    #pragma unroll
                    for (int rr = 0; rr < 4; ++rr){
                        int r = wid*4 + rr;
                        float px = pe[r][0], py = pe[r][1], pz = pe[r][2];
                        float ox = fmaxf(fmaf(px, wx.x, fmaf(py, wy.x, fmaf(pz, wz.x, bb.x))), 0.f) * sf4.x;
                        float oy = fmaxf(fmaf(px, wx.y, fmaf(py, wy.y, fmaf(pz, wz.y, bb.y))), 0.f) * sf4.y;
                        float oz = fmaxf(fmaf(px, wx.z, fmaf(py, wy.z, fmaf(pz, wz.z, bb.z))), 0.f) * sf4.z;
                        float ow = fmaxf(fmaf(px, wx.w, fmaf(py, wy.w, fmaf(pz, wz.w, bb.w))), 0.f) * sf4.w;
                        __nv_bfloat162 pA = __floats2bfloat162_rn(ox, oy);
                        __nv_bfloat162 pB = __floats2bfloat162_rn(oz, ow);
                        uint2 pk = make_uint2(*reinterpret_cast<uint32_t*>(&pA),
                                              *reinterpret_cast<uint32_t*>(&pB));
                        *reinterpret_cast<uint2*>(&hb2[r*(HBS/2) + (c4 >> 1)]) = pk;
                    }
                }
                __syncthreads();   // h published before A-frag reads

                // ---- two residual GEMMs, pipelined chunk stream (no per-chunk CTA barrier)
                #pragma unroll 1
                for (int gg = 0; gg < 2; ++gg){
                    const float* bias_s = gg ? b3s : b2s;
                    const int lo = gg*NCH;

                    float acc[2][8][4];
                    #pragma unroll
                    for (int m = 0; m < 2; ++m)
                        #pragma unroll
                        for (int j = 0; j < 8; ++j)
                            #pragma unroll
                            for (int q = 0; q < 4; ++q) acc[m][j][q] = 0.f;

                    #pragma unroll 1
                    for (int c = 0; c < NCH; ++c){
                        const int t = lo + c;
                        if (tid == 0 && t + 2 < 2*NCH) issue(t + 2);

                        uint32_t j = (gb + (uint32_t)t) % NBUF;
                        mbar_wait(mbarF + j*8, (cful >> j) & 1u);
                        cful ^= (1u << j);
                        const uint32_t wcu = wc_u32 + j*CHBYTES;

                        // A fragments: [m][s2][4]
                        uint32_t Afr[2][2][4];
                        #pragma unroll
                        for (int m = 0; m < 2; ++m)
                            #pragma unroll
                            for (int s2 = 0; s2 < 2; ++s2){
                                uint32_t addr = hb_u32 +
                                    (((uint32_t)(rbase + 16*m) + a_lrow)*HBS + (uint32_t)(c*KCH + s2*16) + a_koff)*2u;
                                LDMX4(Afr[m][s2], addr);
                            }

                        #pragma unroll
                        for (int s2 = 0; s2 < 2; ++s2){
                            #pragma unroll
                            for (int jj = 0; jj < 4; ++jj){
                                uint32_t Bf[4];
                                uint32_t addr = wcu +
                                    (((uint32_t)(colbase + 16*jj) + b_lrow)*WKP + (uint32_t)(s2*16) + b_koff)*2u;
                                LDMX4(Bf, addr);
                                MMA_BF16(acc[0][2*jj],   Afr[0][s2], Bf[0], Bf[1]);
                                MMA_BF16(acc[0][2*jj+1], Afr[0][s2], Bf[2], Bf[3]);
                                MMA_BF16(acc[1][2*jj],   Afr[1][s2], Bf[0], Bf[1]);
                                MMA_BF16(acc[1][2*jj+1], Afr[1][s2], Bf[2], Bf[3]);
                            }
                        }
                        if (lane == 0) MBAR_ARRIVE(mbarE + j*8);
                    }
                    __syncthreads();   // all warps consumed all chunks before h rewritten

                    // epilogue: h = bf16(relu(acc + bias) + h), in place (thread-owned cells)
                    #pragma unroll
                    for (int m = 0; m < 2; ++m){
                        int r = rbase + 16*m + g;
                        #pragma unroll
                        for (int j = 0; j < 8; ++j){
                            int cc = colbase + 8*j + 2*tig;
                            float bi0 = bias_s[cc], bi1 = bias_s[cc+1];
                            #pragma unroll
                            for (int hh = 0; hh < 2; ++hh){
                                uint32_t* hp = &hb2[(r + 8*hh)*(HBS/2) + (cc >> 1)];
                                __nv_bfloat162 old = *reinterpret_cast<__nv_bfloat162*>(hp);
                                float nx = fmaxf(acc[m][j][2*hh]   + bi0, 0.f) + __bfloat162float(old.x);
                                float ny = fmaxf(acc[m][j][2*hh+1] + bi1, 0.f) + __bfloat162float(old.y);
                                __nv_bfloat162 nv = __floats2bfloat162_rn(nx, ny);
                                *hp = *reinterpret_cast<uint32_t*>(&nv);
                            }
                        }
                    }
                    __syncthreads();   // h published before next consumer
                }
                gb += 2*NCH;

                // ---- stage 4: kcur = tanh(h @ W4^T + b4); warp w -> rows 4w..4w+3
                {
                    float a[4][3];
                    #pragma unroll
                    for (int rr = 0; rr < 4; ++rr){ a[rr][0]=0.f; a[rr][1]=0.f; a[rr][2]=0.f; }
                    #pragma unroll 2
                    for (int i = 0; i < 8; ++i){
                        int idx = lane + i*32;          // bf16-pair index
                        float w00 = w4s[2*idx],        w01 = w4s[2*idx+1];
                        float w10 = w4s[512 + 2*idx],  w11 = w4s[512 + 2*idx+1];
                        float w20 = w4s[1024 + 2*idx], w21 = w4s[1024 + 2*idx+1];
                        #pragma unroll
                        for (int rr = 0; rr < 4; ++rr){
                            uint32_t pv = hb2[(wid*4 + rr)*(HBS/2) + idx];
                            __nv_bfloat162 hv = *reinterpret_cast<__nv_bfloat162*>(&pv);
                            float hx = __bfloat162float(hv.x), hy = __bfloat162float(hv.y);
                            a[rr][0] = fmaf(hx, w00, fmaf(hy, w01, a[rr][0]));
                            a[rr][1] = fmaf(hx, w10, fmaf(hy, w11, a[rr][1]));
                            a[rr][2] = fmaf(hx, w20, fmaf(hy, w21, a[rr][2]));
                        }
                    }
                    #pragma unroll
                    for (int rr = 0; rr < 4; ++rr){
                        #pragma unroll
                        for (int j = 0; j < 3; ++j){
                            float v = a[rr][j];
                            #pragma unroll
                            for (int off = 16; off > 0; off >>= 1)
                                v += __shfl_xor_sync(0xffffffffu, v, off);
                            if (lane == 0) kcur[wid*4 + rr][j] = tanhf(v + B4[j]);
                        }
                    }
                }
                __syncthreads();

                // ---- RK4 state update
                if (tid < ROWS*3){
                    int r = tid/3, j = tid - r*3;
                    float k = kcur[r][j];
                    if (s == 0){ ksum[r][j] = k;            pe[r][j] = fmaf(0.5f*dt, k, p0[r][j]); }
                    else if (s == 1){ ksum[r][j] += 2.f*k;  pe[r][j] = fmaf(0.5f*dt, k, p0[r][j]); }
                    else if (s == 2){ ksum[r][j] += 2.f*k;  pe[r][j] = fmaf(dt, k, p0[r][j]); }
                    else { float p = fmaf(dt/6.f, ksum[r][j] + k, p0[r][j]); p0[r][j] = p; pe[r][j] = p; }
                }
                __syncthreads();
            }
        }
    }

    if (tid < ROWS*3){
        int r = tid/3, j = tid - r*3;
        x_out[(base + r)*3 + j] = p0[r][j];
    }
    __syncthreads();
    if (tid == 0){
        #pragma unroll
        for (int j = 0; j < NBUF; ++j){ MBAR_INVAL(mbarF + j*8); MBAR_INVAL(mbarE + j*8); }
    }
}

extern "C" void kernel_launch(void* const* d_in, const int* in_sizes, int n_in,
                              void* d_out, int out_size)
{
    const float* code   = (const float*)d_in[0];
    const float* x      = (const float*)d_in[1];
    const float* f1_l1w = (const float*)d_in[2];
    const float* f1_l1b = (const float*)d_in[3];
    const float* f1_l2w = (const float*)d_in[4];
    const float* f1_l2b = (const float*)d_in[5];
    const float* f1_l3w = (const float*)d_in[6];
    const float* f1_l3b = (const float*)d_in[7];
    const float* f1_l4w = (const float*)d_in[8];
    const float* f1_l4b = (const float*)d_in[9];
    const float* f1_cw  = (const float*)d_in[10];
    const float* f1_cb  = (const float*)d_in[11];
    const float* f2_l1w = (const float*)d_in[12];
    const float* f2_l1b = (const float*)d_in[13];
    const float* f2_l2w = (const float*)d_in[14];
    const float* f2_l2b = (const float*)d_in[15];
    const float* f2_l3w = (const float*)d_in[16];
    const float* f2_l3b = (const float*)d_in[17];
    const float* f2_l4w = (const float*)d_in[18];
    const float* f2_l4b = (const float*)d_in[19];
    const float* f2_cw  = (const float*)d_in[20];
    const float* f2_cb  = (const float*)d_in[21];
    float* out = (float*)d_out;

    const int smem_bytes = 1024 + ROWS*HBS*2 + NBUF*CHBYTES + 5120*4;   // ~211 KB
    cudaFuncSetAttribute(deform_kernel, cudaFuncAttributeMaxDynamicSharedMemorySize, smem_bytes);

    prep_w<<<dim3(NCH, 4), NT>>>(f1_l2w, f1_l3w, f2_l2w, f2_l3w);
    sf_kernel<<<dim3(4, 2), HDIM>>>(code, f1_cw, f1_cb, f2_cw, f2_cb);

    const int n_blocks = (4 * 4096) / ROWS;  // 256
    deform_kernel<<<n_blocks, NT, smem_bytes>>>(
        x, out,
        f1_l1w, f1_l1b, f1_l2b, f1_l3b, f1_l4w, f1_l4b,
        f2_l1w, f2_l1b, f2_l2b, f2_l3b, f2_l4w, f2_l4b);
}